// round 16
// baseline (speedup 1.0000x reference)
#include <cuda_runtime.h>
#include <cuda_fp16.h>
#include <cstdint>
#include <cstddef>

#define NNODES 8192
#define NN4 (NNODES / 4)
#define INF_ 256
#define OUTF 64
#define ALPHA 0.2f
#define LOG2E 1.4426950408889634f
#define PSCALE 256.0f

// ---------------- device scratch ----------------
__device__ __align__(16) __half g_hpH[(size_t)NNODES * 72]; // [node][72]: h' 0-63, ones 64, pad 65-71
__device__ float g_s1[NNODES];
__device__ float g_B[NNODES];            // exp(s2_j)
__device__ float g_D[NNODES];            // exp(ALPHA*s2_j)
__device__ float g_s2part[128];          // per-CTA max of s2
__device__ unsigned g_sync;              // monotonic global-barrier counter

// ---------------- helpers ----------------
__device__ __forceinline__ uint32_t smem_u32(const void* p) {
    uint32_t a;
    asm("{ .reg .u64 t; cvta.to.shared.u64 t, %1; cvt.u32.u64 %0, t; }" : "=r"(a) : "l"(p));
    return a;
}
__device__ __forceinline__ void ldsm_x4(unsigned* r, const void* p) {
    unsigned a = smem_u32(p);
    asm volatile("ldmatrix.sync.aligned.m8n8.x4.shared.b16 {%0,%1,%2,%3},[%4];"
                 : "=r"(r[0]), "=r"(r[1]), "=r"(r[2]), "=r"(r[3]) : "r"(a));
}
__device__ __forceinline__ void ldsm_x4t(unsigned* r, const void* p) {
    unsigned a = smem_u32(p);
    asm volatile("ldmatrix.sync.aligned.m8n8.x4.trans.shared.b16 {%0,%1,%2,%3},[%4];"
                 : "=r"(r[0]), "=r"(r[1]), "=r"(r[2]), "=r"(r[3]) : "r"(a));
}
__device__ __forceinline__ void ldsm_x2t(unsigned* r, const void* p) {
    unsigned a = smem_u32(p);
    asm volatile("ldmatrix.sync.aligned.m8n8.x2.trans.shared.b16 {%0,%1},[%2];"
                 : "=r"(r[0]), "=r"(r[1]) : "r"(a));
}
__device__ __forceinline__ void mma_16816(float* c, const unsigned* a, const unsigned* b) {
    asm volatile(
        "mma.sync.aligned.m16n8k16.row.col.f32.f16.f16.f32 "
        "{%0,%1,%2,%3},{%4,%5,%6,%7},{%8,%9},{%0,%1,%2,%3};"
        : "+f"(c[0]), "+f"(c[1]), "+f"(c[2]), "+f"(c[3])
        : "r"(a[0]), "r"(a[1]), "r"(a[2]), "r"(a[3]), "r"(b[0]), "r"(b[1]));
}
// named barriers: producers arrive (non-blocking), consumers sync (blocking). 512 = whole CTA.
__device__ __forceinline__ void nbar_arrive(int id) {
    asm volatile("bar.arrive %0, 512;" ::"r"(id) : "memory");
}
__device__ __forceinline__ void nbar_sync(int id) {
    asm volatile("bar.sync %0, 512;" ::"r"(id) : "memory");
}

// ---------------- gat smem layout (bytes) ----------------
// main loop: sP 4x[64x136]h = 69632 | sB 5x[128x72]h = 92160 | sA/sC/sT/sL 1024
// prep phase aliases the front (sXh 33792 + sWh 36864 + 1024).
#define OFF_P 0
#define P_HALF (64 * 136)
#define OFF_B 69632
#define B_HALF (128 * 72)
#define OFF_F (69632 + 92160)
#define SMEM_TOTAL (OFF_F + 1024)

#define PXH_OFF 0
#define PWH_OFF 33792
#define PA1_OFF (33792 + 36864)
#define PA2_OFF (PA1_OFF + 256)
#define PMAX_OFF (PA2_OFF + 256)

// ---------------- fused prep+GAT: 128 CTAs x 64 rows, warp-specialized, 4-deep ----------------
__global__ __launch_bounds__(512, 1) void gat_kernel(const float* __restrict__ X,
                                                     const int* __restrict__ adj,
                                                     const float* __restrict__ W,
                                                     const float* __restrict__ a1,
                                                     const float* __restrict__ a2,
                                                     float* __restrict__ out) {
    extern __shared__ char smem[];
    int t = threadIdx.x;
    int w = t >> 5, lane = t & 31;
    int I0 = blockIdx.x * 64;

    // ================= PHASE 1: prep this CTA's 64-row slice =================
    {
        __half* sXh = reinterpret_cast<__half*>(smem + PXH_OFF);
        __half* sWh = reinterpret_cast<__half*>(smem + PWH_OFF);
        float* sA1 = reinterpret_cast<float*>(smem + PA1_OFF);
        float* sA2 = reinterpret_cast<float*>(smem + PA2_OFF);
        float* sMax = reinterpret_cast<float*>(smem + PMAX_OFF);

        for (int idx = t; idx < 64 * 64; idx += 512) {
            int rr = idx >> 6, cc4 = idx & 63;
            float4 v = *reinterpret_cast<const float4*>(&X[(size_t)(I0 + rr) * INF_ + cc4 * 4]);
            half2 h0 = __floats2half2_rn(v.x, v.y);
            half2 h1 = __floats2half2_rn(v.z, v.w);
            uint2 uu;
            uu.x = *reinterpret_cast<unsigned*>(&h0);
            uu.y = *reinterpret_cast<unsigned*>(&h1);
            *reinterpret_cast<uint2*>(&sXh[rr * 264 + cc4 * 4]) = uu;
        }
        for (int idx = t; idx < 256 * 16; idx += 512) {
            int kk = idx >> 4, cc4 = idx & 15;
            float4 v = *reinterpret_cast<const float4*>(&W[(size_t)kk * OUTF + cc4 * 4]);
            half2 h0 = __floats2half2_rn(v.x, v.y);
            half2 h1 = __floats2half2_rn(v.z, v.w);
            uint2 uu;
            uu.x = *reinterpret_cast<unsigned*>(&h0);
            uu.y = *reinterpret_cast<unsigned*>(&h1);
            *reinterpret_cast<uint2*>(&sWh[kk * 72 + cc4 * 4]) = uu;
        }
        if (t < 64) sA1[t] = a1[t];
        else if (t < 128) sA2[t - 64] = a2[t - 64];
        __syncthreads();

        if (w < 4) {
            int cshift = (lane >> 4) << 3;
            float acc[8][4];
#pragma unroll
            for (int i = 0; i < 8; i++)
#pragma unroll
                for (int j = 0; j < 4; j++) acc[i][j] = 0.f;

#pragma unroll
            for (int ks = 0; ks < 16; ks++) {
                unsigned a[4];
                ldsm_x4(a, &sXh[(w * 16 + (lane & 15)) * 264 + ks * 16 + cshift]);
                int brow = ks * 16 + (lane & 15);
#pragma unroll
                for (int nt2 = 0; nt2 < 4; nt2++) {
                    unsigned bb[4];
                    ldsm_x4t(bb, &sWh[brow * 72 + nt2 * 16 + cshift]);
                    mma_16816(acc[2 * nt2], a, bb);
                    mma_16816(acc[2 * nt2 + 1], a, bb + 2);
                }
            }

            int g = lane >> 2, tt = lane & 3;
            int r0l = w * 16 + g, r1l = r0l + 8;
            size_t row0 = (size_t)(I0 + r0l), row1 = (size_t)(I0 + r1l);
            float s1a = 0.f, s2a = 0.f, s1b = 0.f, s2b = 0.f;
#pragma unroll
            for (int j = 0; j < 8; j++) {
                int cb = j * 8 + 2 * tt;
                half2 h01 = __floats2half2_rn(acc[j][0], acc[j][1]);
                half2 h23 = __floats2half2_rn(acc[j][2], acc[j][3]);
                *reinterpret_cast<unsigned*>(&g_hpH[row0 * 72 + cb]) = *reinterpret_cast<unsigned*>(&h01);
                *reinterpret_cast<unsigned*>(&g_hpH[row1 * 72 + cb]) = *reinterpret_cast<unsigned*>(&h23);
                float w10 = sA1[cb], w11 = sA1[cb + 1];
                float w20 = sA2[cb], w21 = sA2[cb + 1];
                s1a += acc[j][0] * w10 + acc[j][1] * w11;
                s2a += acc[j][0] * w20 + acc[j][1] * w21;
                s1b += acc[j][2] * w10 + acc[j][3] * w11;
                s2b += acc[j][2] * w20 + acc[j][3] * w21;
            }
            if (tt == 0) {
                uint4 ones = make_uint4(0x00003C00u, 0u, 0u, 0u);
                *reinterpret_cast<uint4*>(&g_hpH[row0 * 72 + 64]) = ones;
                *reinterpret_cast<uint4*>(&g_hpH[row1 * 72 + 64]) = ones;
            }
#pragma unroll
            for (int o = 2; o; o >>= 1) {
                s1a += __shfl_down_sync(0xffffffffu, s1a, o, 4);
                s2a += __shfl_down_sync(0xffffffffu, s2a, o, 4);
                s1b += __shfl_down_sync(0xffffffffu, s1b, o, 4);
                s2b += __shfl_down_sync(0xffffffffu, s2b, o, 4);
            }
            if (tt == 0) {
                g_s1[row0] = s1a;
                g_B[row0] = exp2f(LOG2E * s2a);
                g_D[row0] = exp2f(ALPHA * LOG2E * s2a);
                sMax[r0l] = s2a;
                g_s1[row1] = s1b;
                g_B[row1] = exp2f(LOG2E * s2b);
                g_D[row1] = exp2f(ALPHA * LOG2E * s2b);
                sMax[r1l] = s2b;
            }
        }
        __syncthreads();
        if (t == 0) {
            float m = sMax[0];
#pragma unroll
            for (int i = 1; i < 64; i++) m = fmaxf(m, sMax[i]);
            g_s2part[blockIdx.x] = m;
        }
    }

    // ================= global barrier (all 128 CTAs co-resident) =================
    if (t == 0) {
        __threadfence();
        unsigned a = atomicAdd(&g_sync, 1u);
        unsigned target = (a / 128u + 1u) * 128u;
        unsigned v;
        do {
            asm volatile("ld.global.acquire.gpu.u32 %0, [%1];" : "=r"(v) : "l"(&g_sync));
        } while (v < target);
    }
    __syncthreads();

    // ================= PHASE 2: GAT main (R13 structure, named-barrier handoff) =================
    __half* sP = reinterpret_cast<__half*>(smem + OFF_P);
    __half* sB = reinterpret_cast<__half*>(smem + OFF_B);
    float* sA = reinterpret_cast<float*>(smem + OFF_F);
    float* sC = sA + 64;
    float* sT = sA + 128;
    float* sL = sA + 192;
    float* sRed = reinterpret_cast<float*>(smem);  // aliases sP (prologue only)

    if (t < 128) sRed[t] = g_s2part[t];
    __syncthreads();
    if (t < 32) {
        float m = sRed[t];
#pragma unroll
        for (int k = 1; k < 4; k++) m = fmaxf(m, sRed[t + 32 * k]);
#pragma unroll
        for (int o = 16; o; o >>= 1) m = fmaxf(m, __shfl_xor_sync(0xffffffffu, m, o));
        if (t == 0) sRed[0] = m;
    }
    __syncthreads();
    float S2max = sRed[0];
    __syncthreads();

    if (t < 64) {
        float s1 = g_s1[I0 + t];
        float v = s1 + S2max;
        float m = fmaxf(v, ALPHA * v);          // >= row max of leaky -> weights <= 1
        sA[t] = PSCALE * exp2f(LOG2E * (s1 - m));
        sC[t] = PSCALE * exp2f(LOG2E * (ALPHA * s1 - m));
        sT[t] = exp2f(-LOG2E * s1);
    }
    __syncthreads();

    const int4* adj4 = reinterpret_cast<const int4*>(adj);

    if (w >= 8) {
        // ================= PRODUCERS (warps 8-15) =================
        int pw = w - 8;                 // owns P rows pw*8 .. pw*8+7
        int jt = lane * 4;
        int pt = t - 256;

        float Ai[8], Ci[8], Ti[8];
#pragma unroll
        for (int rr = 0; rr < 8; rr++) {
            Ai[rr] = sA[pw * 8 + rr];
            Ci[rr] = sC[pw * 8 + rr];
            Ti[rr] = sT[pw * 8 + rr];
        }

        for (int idx = pt; idx < 128 * 9; idx += 256) {
            int rrow = idx / 9, seg = idx - rrow * 9;
            unsigned dst = smem_u32(&sB[rrow * 72 + seg * 8]);
            const __half* src = &g_hpH[(size_t)rrow * 72 + seg * 8];
            asm volatile("cp.async.cg.shared.global [%0], [%1], 16;" ::"r"(dst), "l"(src));
        }
        asm volatile("cp.async.commit_group;");
        int4 cur[8];
#pragma unroll
        for (int rr = 0; rr < 8; rr++)
            cur[rr] = adj4[(size_t)(I0 + pw * 8 + rr) * NN4 + lane];

        int jbn = 1;   // sB buffer for next issued chunk (c+1), mod 5
        for (int c = 0; c < 64; c++) {
            int ip = c & 3;
            if (c >= 4) nbar_sync(5 + ip);     // wait empty[ip]

            // drain sB chunk c (issued >=1 chunk ago; already landed — cheap)
            asm volatile("cp.async.wait_group 0;");

            // P generation: zero-MUFU separable softmax numerator, adj-masked
            __half* sPc = sP + ip * P_HALF;
            float4 Bv = *reinterpret_cast<const float4*>(&g_B[c * 128 + jt]);
            float4 Dv = *reinterpret_cast<const float4*>(&g_D[c * 128 + jt]);
#pragma unroll
            for (int rr = 0; rr < 8; rr++) {
                int i = pw * 8 + rr;
                int4 av = cur[rr];
                float v0 = (Bv.x >= Ti[rr]) ? Ai[rr] * Bv.x : Ci[rr] * Dv.x; if (av.x <= 0) v0 = 0.f;
                float v1 = (Bv.y >= Ti[rr]) ? Ai[rr] * Bv.y : Ci[rr] * Dv.y; if (av.y <= 0) v1 = 0.f;
                float v2 = (Bv.z >= Ti[rr]) ? Ai[rr] * Bv.z : Ci[rr] * Dv.z; if (av.z <= 0) v2 = 0.f;
                float v3 = (Bv.w >= Ti[rr]) ? Ai[rr] * Bv.w : Ci[rr] * Dv.w; if (av.w <= 0) v3 = 0.f;
                half2 h01 = __floats2half2_rn(v0, v1);
                half2 h23 = __floats2half2_rn(v2, v3);
                uint2 uu;
                uu.x = *reinterpret_cast<unsigned*>(&h01);
                uu.y = *reinterpret_cast<unsigned*>(&h23);
                *reinterpret_cast<uint2*>(&sPc[i * 136 + jt]) = uu;
            }

            nbar_arrive(1 + ip);               // signal full[ip] (non-blocking)

            if (c < 63) {
                __half* dstb = sB + jbn * B_HALF;
                for (int idx = pt; idx < 128 * 9; idx += 256) {
                    int rrow = idx / 9, seg = idx - rrow * 9;
                    unsigned dst = smem_u32(&dstb[rrow * 72 + seg * 8]);
                    const __half* src = &g_hpH[(size_t)(c * 128 + 128 + rrow) * 72 + seg * 8];
                    asm volatile("cp.async.cg.shared.global [%0], [%1], 16;" ::"r"(dst), "l"(src));
                }
                asm volatile("cp.async.commit_group;");
#pragma unroll
                for (int rr = 0; rr < 8; rr++)
                    cur[rr] = adj4[(size_t)(I0 + pw * 8 + rr) * NN4 + (c + 1) * 32 + lane];
                if (++jbn == 5) jbn = 0;
            }
        }
        return;
    }

    // ================= CONSUMERS (warps 0-7): 4 row-groups x 2 col-groups =================
    int rg = w & 3, cg = w >> 2;
    int cshift = (lane >> 4) << 3;

    float acc[5][4];
#pragma unroll
    for (int i = 0; i < 5; i++)
#pragma unroll
        for (int j = 0; j < 4; j++) acc[i][j] = 0.f;

    int ib = 0;   // sB buffer index = c % 5
    for (int c = 0; c < 64; c++) {
        int ip = c & 3;
        nbar_sync(1 + ip);                     // wait full[ip]
        const __half* sPc = sP + ip * P_HALF;
        const __half* sBc = sB + ib * B_HALF;

#pragma unroll
        for (int ks = 0; ks < 8; ks++) {
            unsigned a[4];
            ldsm_x4(a, &sPc[(rg * 16 + (lane & 15)) * 136 + ks * 16 + cshift]);
            int brow = ks * 16 + (lane & 15);
            unsigned bb[4];
            if (cg == 0) {
                ldsm_x4t(bb, &sBc[brow * 72 + 0 + cshift]);
                mma_16816(acc[0], a, bb); mma_16816(acc[1], a, bb + 2);
                ldsm_x4t(bb, &sBc[brow * 72 + 16 + cshift]);
                mma_16816(acc[2], a, bb); mma_16816(acc[3], a, bb + 2);
                ldsm_x2t(bb, &sBc[brow * 72 + 32]);
                mma_16816(acc[4], a, bb);
            } else {
                ldsm_x4t(bb, &sBc[brow * 72 + 40 + cshift]);
                mma_16816(acc[0], a, bb); mma_16816(acc[1], a, bb + 2);
                ldsm_x4t(bb, &sBc[brow * 72 + 56 + cshift]);
                mma_16816(acc[2], a, bb); mma_16816(acc[3], a, bb + 2);
            }
        }
        nbar_arrive(5 + ip);                   // signal empty[ip] (non-blocking)
        if (++ib == 5) ib = 0;
    }

    // ---- epilogue: denominator l = ones column (col 64 = cg1 acc[3], in-tile col 0) ----
    if (cg == 1 && (lane & 3) == 0) {
        int g = lane >> 2;
        sL[rg * 16 + g]     = acc[3][0];
        sL[rg * 16 + g + 8] = acc[3][2];
    }
    asm volatile("bar.sync 9, 256;" ::: "memory");   // consumers only

    int g = lane >> 2, tt = lane & 3;
    int r0 = rg * 16 + g, r1 = r0 + 8;
    float inv0 = 1.f / sL[r0];
    float inv1 = 1.f / sL[r1];
    int ntiles = cg ? 3 : 5;
    int cbase  = cg ? 40 : 0;
    for (int ti = 0; ti < ntiles; ti++) {
        int cb = cbase + ti * 8 + 2 * tt;
        float o00 = acc[ti][0] * inv0, o01 = acc[ti][1] * inv0;
        float o10 = acc[ti][2] * inv1, o11 = acc[ti][3] * inv1;
        o00 = o00 > 0.f ? o00 : expm1f(o00);
        o01 = o01 > 0.f ? o01 : expm1f(o01);
        o10 = o10 > 0.f ? o10 : expm1f(o10);
        o11 = o11 > 0.f ? o11 : expm1f(o11);
        out[(size_t)(I0 + r0) * OUTF + cb]     = o00;
        out[(size_t)(I0 + r0) * OUTF + cb + 1] = o01;
        out[(size_t)(I0 + r1) * OUTF + cb]     = o10;
        out[(size_t)(I0 + r1) * OUTF + cb + 1] = o11;
    }
}

extern "C" void kernel_launch(void* const* d_in, const int* in_sizes, int n_in,
                              void* d_out, int out_size) {
    const float* X   = (const float*)d_in[0];
    const int*   adj = (const int*)d_in[1];
    const float* W   = (const float*)d_in[2];
    const float* a1  = (const float*)d_in[3];
    const float* a2  = (const float*)d_in[4];
    float* out = (float*)d_out;

    static int smem_set = 0;
    if (!smem_set) {
        cudaFuncSetAttribute(gat_kernel, cudaFuncAttributeMaxDynamicSharedMemorySize,
                             SMEM_TOTAL);
        smem_set = 1;
    }

    gat_kernel<<<128, 512, SMEM_TOTAL>>>(X, adj, W, a1, a2, out);
}

// round 17
// speedup vs baseline: 1.1256x; 1.1256x over previous
#include <cuda_runtime.h>
#include <cuda_fp16.h>
#include <cstdint>
#include <cstddef>

#define NNODES 8192
#define NN4 (NNODES / 4)
#define INF_ 256
#define OUTF 64
#define ALPHA 0.2f
#define LOG2E 1.4426950408889634f
#define PSCALE 256.0f

// ---------------- device scratch ----------------
__device__ __align__(16) __half g_hpH[(size_t)NNODES * 72]; // [node][72]: h' 0-63, ones 64, pad 65-71
__device__ float g_s1[NNODES];
__device__ float g_B[NNODES];            // exp(s2_j)
__device__ float g_D[NNODES];            // exp(ALPHA*s2_j)
__device__ float g_s2part[128];          // per-CTA max of s2
__device__ unsigned g_sync;              // monotonic global-barrier counter

// ---------------- mma / barrier helpers ----------------
__device__ __forceinline__ uint32_t smem_u32(const void* p) {
    uint32_t a;
    asm("{ .reg .u64 t; cvta.to.shared.u64 t, %1; cvt.u32.u64 %0, t; }" : "=r"(a) : "l"(p));
    return a;
}
__device__ __forceinline__ void ldsm_x4(unsigned* r, const void* p) {
    unsigned a = smem_u32(p);
    asm volatile("ldmatrix.sync.aligned.m8n8.x4.shared.b16 {%0,%1,%2,%3},[%4];"
                 : "=r"(r[0]), "=r"(r[1]), "=r"(r[2]), "=r"(r[3]) : "r"(a));
}
__device__ __forceinline__ void ldsm_x4t(unsigned* r, const void* p) {
    unsigned a = smem_u32(p);
    asm volatile("ldmatrix.sync.aligned.m8n8.x4.trans.shared.b16 {%0,%1,%2,%3},[%4];"
                 : "=r"(r[0]), "=r"(r[1]), "=r"(r[2]), "=r"(r[3]) : "r"(a));
}
__device__ __forceinline__ void ldsm_x2t(unsigned* r, const void* p) {
    unsigned a = smem_u32(p);
    asm volatile("ldmatrix.sync.aligned.m8n8.x2.trans.shared.b16 {%0,%1},[%2];"
                 : "=r"(r[0]), "=r"(r[1]) : "r"(a));
}
__device__ __forceinline__ void mma_16816(float* c, const unsigned* a, const unsigned* b) {
    asm volatile(
        "mma.sync.aligned.m16n8k16.row.col.f32.f16.f16.f32 "
        "{%0,%1,%2,%3},{%4,%5,%6,%7},{%8,%9},{%0,%1,%2,%3};"
        : "+f"(c[0]), "+f"(c[1]), "+f"(c[2]), "+f"(c[3])
        : "r"(a[0]), "r"(a[1]), "r"(a[2]), "r"(a[3]), "r"(b[0]), "r"(b[1]));
}
__device__ __forceinline__ void mbar_init(uint32_t a, uint32_t n) {
    asm volatile("mbarrier.init.shared.b64 [%0], %1;" ::"r"(a), "r"(n) : "memory");
}
__device__ __forceinline__ void mbar_arrive(uint32_t a) {
    asm volatile("mbarrier.arrive.shared.b64 _, [%0];" ::"r"(a) : "memory");
}
__device__ __forceinline__ void mbar_wait(uint32_t mbar, uint32_t parity) {
    uint32_t done;
    asm volatile(
        "{ .reg .pred p; mbarrier.try_wait.parity.shared::cta.b64 p, [%1], %2; selp.b32 %0,1,0,p; }"
        : "=r"(done) : "r"(mbar), "r"(parity) : "memory");
    if (!done) {
        asm volatile(
            "{ .reg .pred P1;\n"
            "WL_%=: mbarrier.try_wait.parity.shared::cta.b64 P1, [%0], %1;\n"
            "@P1 bra.uni WD_%=;\n bra.uni WL_%=;\n WD_%=: }"
            ::"r"(mbar), "r"(parity) : "memory");
    }
}
// streaming int4 load: evict-first in L1/L2 (adj has zero reuse)
__device__ __forceinline__ int4 ldg_cs4(const int4* p) {
    int4 v;
    asm volatile("ld.global.cs.v4.s32 {%0,%1,%2,%3}, [%4];"
                 : "=r"(v.x), "=r"(v.y), "=r"(v.z), "=r"(v.w) : "l"(p));
    return v;
}

// ---------------- gat smem layout (bytes) ----------------
// main loop: sP 4x[64x136]h = 69632 | sB 5x[128x72]h = 92160 | sA/sC/sT/sL 1024 | mbar 64
// prep phase aliases the front of this region (sXh 33792 + sWh 36864 + 1024).
#define OFF_P 0
#define P_HALF (64 * 136)
#define OFF_B 69632
#define B_HALF (128 * 72)
#define OFF_F (69632 + 92160)
#define OFF_MB (OFF_F + 1024)
#define SMEM_TOTAL (OFF_MB + 64)

#define PXH_OFF 0
#define PWH_OFF 33792
#define PA1_OFF (33792 + 36864)
#define PA2_OFF (PA1_OFF + 256)
#define PMAX_OFF (PA2_OFF + 256)

// ---------------- fused prep+GAT: 128 CTAs x 64 rows, warp-specialized, 4-deep ----------------
__global__ __launch_bounds__(512, 1) void gat_kernel(const float* __restrict__ X,
                                                     const int* __restrict__ adj,
                                                     const float* __restrict__ W,
                                                     const float* __restrict__ a1,
                                                     const float* __restrict__ a2,
                                                     float* __restrict__ out) {
    extern __shared__ char smem[];
    int t = threadIdx.x;
    int w = t >> 5, lane = t & 31;
    int I0 = blockIdx.x * 64;

    // ================= PHASE 1: prep this CTA's 64-row slice =================
    {
        __half* sXh = reinterpret_cast<__half*>(smem + PXH_OFF);
        __half* sWh = reinterpret_cast<__half*>(smem + PWH_OFF);
        float* sA1 = reinterpret_cast<float*>(smem + PA1_OFF);
        float* sA2 = reinterpret_cast<float*>(smem + PA2_OFF);
        float* sMax = reinterpret_cast<float*>(smem + PMAX_OFF);

        for (int idx = t; idx < 64 * 64; idx += 512) {
            int rr = idx >> 6, cc4 = idx & 63;
            float4 v = *reinterpret_cast<const float4*>(&X[(size_t)(I0 + rr) * INF_ + cc4 * 4]);
            half2 h0 = __floats2half2_rn(v.x, v.y);
            half2 h1 = __floats2half2_rn(v.z, v.w);
            uint2 uu;
            uu.x = *reinterpret_cast<unsigned*>(&h0);
            uu.y = *reinterpret_cast<unsigned*>(&h1);
            *reinterpret_cast<uint2*>(&sXh[rr * 264 + cc4 * 4]) = uu;
        }
        for (int idx = t; idx < 256 * 16; idx += 512) {
            int kk = idx >> 4, cc4 = idx & 15;
            float4 v = *reinterpret_cast<const float4*>(&W[(size_t)kk * OUTF + cc4 * 4]);
            half2 h0 = __floats2half2_rn(v.x, v.y);
            half2 h1 = __floats2half2_rn(v.z, v.w);
            uint2 uu;
            uu.x = *reinterpret_cast<unsigned*>(&h0);
            uu.y = *reinterpret_cast<unsigned*>(&h1);
            *reinterpret_cast<uint2*>(&sWh[kk * 72 + cc4 * 4]) = uu;
        }
        if (t < 64) sA1[t] = a1[t];
        else if (t < 128) sA2[t - 64] = a2[t - 64];
        __syncthreads();

        if (w < 4) {
            int cshift = (lane >> 4) << 3;
            float acc[8][4];
#pragma unroll
            for (int i = 0; i < 8; i++)
#pragma unroll
                for (int j = 0; j < 4; j++) acc[i][j] = 0.f;

#pragma unroll
            for (int ks = 0; ks < 16; ks++) {
                unsigned a[4];
                ldsm_x4(a, &sXh[(w * 16 + (lane & 15)) * 264 + ks * 16 + cshift]);
                int brow = ks * 16 + (lane & 15);
#pragma unroll
                for (int nt2 = 0; nt2 < 4; nt2++) {
                    unsigned bb[4];
                    ldsm_x4t(bb, &sWh[brow * 72 + nt2 * 16 + cshift]);
                    mma_16816(acc[2 * nt2], a, bb);
                    mma_16816(acc[2 * nt2 + 1], a, bb + 2);
                }
            }

            int g = lane >> 2, tt = lane & 3;
            int r0l = w * 16 + g, r1l = r0l + 8;
            size_t row0 = (size_t)(I0 + r0l), row1 = (size_t)(I0 + r1l);
            float s1a = 0.f, s2a = 0.f, s1b = 0.f, s2b = 0.f;
#pragma unroll
            for (int j = 0; j < 8; j++) {
                int cb = j * 8 + 2 * tt;
                half2 h01 = __floats2half2_rn(acc[j][0], acc[j][1]);
                half2 h23 = __floats2half2_rn(acc[j][2], acc[j][3]);
                *reinterpret_cast<unsigned*>(&g_hpH[row0 * 72 + cb]) = *reinterpret_cast<unsigned*>(&h01);
                *reinterpret_cast<unsigned*>(&g_hpH[row1 * 72 + cb]) = *reinterpret_cast<unsigned*>(&h23);
                float w10 = sA1[cb], w11 = sA1[cb + 1];
                float w20 = sA2[cb], w21 = sA2[cb + 1];
                s1a += acc[j][0] * w10 + acc[j][1] * w11;
                s2a += acc[j][0] * w20 + acc[j][1] * w21;
                s1b += acc[j][2] * w10 + acc[j][3] * w11;
                s2b += acc[j][2] * w20 + acc[j][3] * w21;
            }
            if (tt == 0) {
                uint4 ones = make_uint4(0x00003C00u, 0u, 0u, 0u);
                *reinterpret_cast<uint4*>(&g_hpH[row0 * 72 + 64]) = ones;
                *reinterpret_cast<uint4*>(&g_hpH[row1 * 72 + 64]) = ones;
            }
#pragma unroll
            for (int o = 2; o; o >>= 1) {
                s1a += __shfl_down_sync(0xffffffffu, s1a, o, 4);
                s2a += __shfl_down_sync(0xffffffffu, s2a, o, 4);
                s1b += __shfl_down_sync(0xffffffffu, s1b, o, 4);
                s2b += __shfl_down_sync(0xffffffffu, s2b, o, 4);
            }
            if (tt == 0) {
                g_s1[row0] = s1a;
                g_B[row0] = exp2f(LOG2E * s2a);
                g_D[row0] = exp2f(ALPHA * LOG2E * s2a);
                sMax[r0l] = s2a;
                g_s1[row1] = s1b;
                g_B[row1] = exp2f(LOG2E * s2b);
                g_D[row1] = exp2f(ALPHA * LOG2E * s2b);
                sMax[r1l] = s2b;
            }
        }
        __syncthreads();
        if (t == 0) {
            float m = sMax[0];
#pragma unroll
            for (int i = 1; i < 64; i++) m = fmaxf(m, sMax[i]);
            g_s2part[blockIdx.x] = m;
        }
    }

    // ================= global barrier (all 128 CTAs co-resident) =================
    if (t == 0) {
        __threadfence();
        unsigned a = atomicAdd(&g_sync, 1u);
        unsigned target = (a / 128u + 1u) * 128u;
        unsigned v;
        do {
            asm volatile("ld.global.acquire.gpu.u32 %0, [%1];" : "=r"(v) : "l"(&g_sync));
        } while (v < target);
    }
    __syncthreads();

    // ================= PHASE 2: GAT main (R13 verbatim + streaming adj) =================
    __half* sP = reinterpret_cast<__half*>(smem + OFF_P);
    __half* sB = reinterpret_cast<__half*>(smem + OFF_B);
    float* sA = reinterpret_cast<float*>(smem + OFF_F);
    float* sC = sA + 64;
    float* sT = sA + 128;
    float* sL = sA + 192;
    float* sRed = reinterpret_cast<float*>(smem);  // aliases sP (prologue only)
    uint32_t mb_u = smem_u32(smem + OFF_MB);

    if (t < 128) sRed[t] = g_s2part[t];
    __syncthreads();
    if (t < 32) {
        float m = sRed[t];
#pragma unroll
        for (int k = 1; k < 4; k++) m = fmaxf(m, sRed[t + 32 * k]);
#pragma unroll
        for (int o = 16; o; o >>= 1) m = fmaxf(m, __shfl_xor_sync(0xffffffffu, m, o));
        if (t == 0) sRed[0] = m;
    }
    __syncthreads();
    float S2max = sRed[0];
    __syncthreads();

    if (t < 64) {
        float s1 = g_s1[I0 + t];
        float v = s1 + S2max;
        float m = fmaxf(v, ALPHA * v);          // >= row max of leaky -> weights <= 1
        sA[t] = PSCALE * exp2f(LOG2E * (s1 - m));
        sC[t] = PSCALE * exp2f(LOG2E * (ALPHA * s1 - m));
        sT[t] = exp2f(-LOG2E * s1);
    }
    if (t == 0) {
#pragma unroll
        for (int i = 0; i < 4; i++) {
            mbar_init(mb_u + i * 8, 8);        // full[i]: 8 producer arrivals
            mbar_init(mb_u + 32 + i * 8, 8);   // empty[i]: 8 consumer arrivals
        }
    }
    __syncthreads();

    const int4* adj4 = reinterpret_cast<const int4*>(adj);

    if (w >= 8) {
        // ================= PRODUCERS (warps 8-15) =================
        int pw = w - 8;                 // owns P rows pw*8 .. pw*8+7
        int jt = lane * 4;
        int pt = t - 256;

        float Ai[8], Ci[8], Ti[8];
#pragma unroll
        for (int rr = 0; rr < 8; rr++) {
            Ai[rr] = sA[pw * 8 + rr];
            Ci[rr] = sC[pw * 8 + rr];
            Ti[rr] = sT[pw * 8 + rr];
        }

        for (int idx = pt; idx < 128 * 9; idx += 256) {
            int rrow = idx / 9, seg = idx - rrow * 9;
            unsigned dst = smem_u32(&sB[rrow * 72 + seg * 8]);
            const __half* src = &g_hpH[(size_t)rrow * 72 + seg * 8];
            asm volatile("cp.async.cg.shared.global [%0], [%1], 16;" ::"r"(dst), "l"(src));
        }
        asm volatile("cp.async.commit_group;");
        int4 cur[8];
#pragma unroll
        for (int rr = 0; rr < 8; rr++)
            cur[rr] = ldg_cs4(&adj4[(size_t)(I0 + pw * 8 + rr) * NN4 + lane]);

        int jbn = 1;   // sB buffer for next issued chunk (c+1), mod 5
        for (int c = 0; c < 64; c++) {
            int ip = c & 3;
            if (c >= 4) mbar_wait(mb_u + 32 + ip * 8, ((c >> 2) + 1) & 1);

            __half* sPc = sP + ip * P_HALF;
            float4 Bv = *reinterpret_cast<const float4*>(&g_B[c * 128 + jt]);
            float4 Dv = *reinterpret_cast<const float4*>(&g_D[c * 128 + jt]);
#pragma unroll
            for (int rr = 0; rr < 8; rr++) {
                int i = pw * 8 + rr;
                int4 av = cur[rr];
                float v0 = (Bv.x >= Ti[rr]) ? Ai[rr] * Bv.x : Ci[rr] * Dv.x; if (av.x <= 0) v0 = 0.f;
                float v1 = (Bv.y >= Ti[rr]) ? Ai[rr] * Bv.y : Ci[rr] * Dv.y; if (av.y <= 0) v1 = 0.f;
                float v2 = (Bv.z >= Ti[rr]) ? Ai[rr] * Bv.z : Ci[rr] * Dv.z; if (av.z <= 0) v2 = 0.f;
                float v3 = (Bv.w >= Ti[rr]) ? Ai[rr] * Bv.w : Ci[rr] * Dv.w; if (av.w <= 0) v3 = 0.f;
                half2 h01 = __floats2half2_rn(v0, v1);
                half2 h23 = __floats2half2_rn(v2, v3);
                uint2 uu;
                uu.x = *reinterpret_cast<unsigned*>(&h01);
                uu.y = *reinterpret_cast<unsigned*>(&h23);
                *reinterpret_cast<uint2*>(&sPc[i * 136 + jt]) = uu;
            }

            asm volatile("cp.async.wait_group 0;");
            __syncwarp();
            if (lane == 0) mbar_arrive(mb_u + ip * 8);

            if (c < 63) {
                __half* dstb = sB + jbn * B_HALF;
                for (int idx = pt; idx < 128 * 9; idx += 256) {
                    int rrow = idx / 9, seg = idx - rrow * 9;
                    unsigned dst = smem_u32(&dstb[rrow * 72 + seg * 8]);
                    const __half* src = &g_hpH[(size_t)(c * 128 + 128 + rrow) * 72 + seg * 8];
                    asm volatile("cp.async.cg.shared.global [%0], [%1], 16;" ::"r"(dst), "l"(src));
                }
                asm volatile("cp.async.commit_group;");
#pragma unroll
                for (int rr = 0; rr < 8; rr++)
                    cur[rr] = ldg_cs4(&adj4[(size_t)(I0 + pw * 8 + rr) * NN4 + (c + 1) * 32 + lane]);
                if (++jbn == 5) jbn = 0;
            }
        }
        return;
    }

    // ================= CONSUMERS (warps 0-7): 4 row-groups x 2 col-groups =================
    int rg = w & 3, cg = w >> 2;
    int cshift = (lane >> 4) << 3;

    float acc[5][4];
#pragma unroll
    for (int i = 0; i < 5; i++)
#pragma unroll
        for (int j = 0; j < 4; j++) acc[i][j] = 0.f;

    int ib = 0;   // sB buffer index = c % 5
    for (int c = 0; c < 64; c++) {
        int ip = c & 3;
        mbar_wait(mb_u + ip * 8, (c >> 2) & 1);
        const __half* sPc = sP + ip * P_HALF;
        const __half* sBc = sB + ib * B_HALF;

#pragma unroll
        for (int ks = 0; ks < 8; ks++) {
            unsigned a[4];
            ldsm_x4(a, &sPc[(rg * 16 + (lane & 15)) * 136 + ks * 16 + cshift]);
            int brow = ks * 16 + (lane & 15);
            unsigned bb[4];
            if (cg == 0) {
                ldsm_x4t(bb, &sBc[brow * 72 + 0 + cshift]);
                mma_16816(acc[0], a, bb); mma_16816(acc[1], a, bb + 2);
                ldsm_x4t(bb, &sBc[brow * 72 + 16 + cshift]);
                mma_16816(acc[2], a, bb); mma_16816(acc[3], a, bb + 2);
                ldsm_x2t(bb, &sBc[brow * 72 + 32]);
                mma_16816(acc[4], a, bb);
            } else {
                ldsm_x4t(bb, &sBc[brow * 72 + 40 + cshift]);
                mma_16816(acc[0], a, bb); mma_16816(acc[1], a, bb + 2);
                ldsm_x4t(bb, &sBc[brow * 72 + 56 + cshift]);
                mma_16816(acc[2], a, bb); mma_16816(acc[3], a, bb + 2);
            }
        }
        __syncwarp();
        if (lane == 0) mbar_arrive(mb_u + 32 + ip * 8);
        if (++ib == 5) ib = 0;
    }

    // ---- epilogue: denominator l = ones column (col 64 = cg1 acc[3], in-tile col 0) ----
    if (cg == 1 && (lane & 3) == 0) {
        int g = lane >> 2;
        sL[rg * 16 + g]     = acc[3][0];
        sL[rg * 16 + g + 8] = acc[3][2];
    }
    asm volatile("bar.sync 1, 256;" ::: "memory");   // consumers only

    int g = lane >> 2, tt = lane & 3;
    int r0 = rg * 16 + g, r1 = r0 + 8;
    float inv0 = 1.f / sL[r0];
    float inv1 = 1.f / sL[r1];
    int ntiles = cg ? 3 : 5;
    int cbase  = cg ? 40 : 0;
    for (int ti = 0; ti < ntiles; ti++) {
        int cb = cbase + ti * 8 + 2 * tt;
        float o00 = acc[ti][0] * inv0, o01 = acc[ti][1] * inv0;
        float o10 = acc[ti][2] * inv1, o11 = acc[ti][3] * inv1;
        o00 = o00 > 0.f ? o00 : expm1f(o00);
        o01 = o01 > 0.f ? o01 : expm1f(o01);
        o10 = o10 > 0.f ? o10 : expm1f(o10);
        o11 = o11 > 0.f ? o11 : expm1f(o11);
        out[(size_t)(I0 + r0) * OUTF + cb]     = o00;
        out[(size_t)(I0 + r0) * OUTF + cb + 1] = o01;
        out[(size_t)(I0 + r1) * OUTF + cb]     = o10;
        out[(size_t)(I0 + r1) * OUTF + cb + 1] = o11;
    }
}

extern "C" void kernel_launch(void* const* d_in, const int* in_sizes, int n_in,
                              void* d_out, int out_size) {
    const float* X   = (const float*)d_in[0];
    const int*   adj = (const int*)d_in[1];
    const float* W   = (const float*)d_in[2];
    const float* a1  = (const float*)d_in[3];
    const float* a2  = (const float*)d_in[4];
    float* out = (float*)d_out;

    static int smem_set = 0;
    if (!smem_set) {
        cudaFuncSetAttribute(gat_kernel, cudaFuncAttributeMaxDynamicSharedMemorySize,
                             SMEM_TOTAL);
        smem_set = 1;
    }

    gat_kernel<<<128, 512, SMEM_TOTAL>>>(X, adj, W, a1, a2, out);
}